// round 1
// baseline (speedup 1.0000x reference)
#include <cuda_runtime.h>
#include <math.h>

#define HS 1080
#define WS 1920
#define OUTW 3840
#define MAXM 192
#define MAXK 512

// Rect table scratch (allocation-free: __device__ globals)
__device__ int   g_rx1[MAXK];
__device__ int   g_ry1[MAXK];
__device__ int   g_rx2[MAXK];
__device__ int   g_ry2[MAXK];
__device__ float g_rval[MAXK];

__global__ void setup_kernel(
    const float* __restrict__ boxes, const float* __restrict__ scores,
    const float* __restrict__ flags,
    const float* __restrict__ boxes_prev, const float* __restrict__ scores_prev,
    const float* __restrict__ flags_prev,
    const int* __restrict__ ids, const int* __restrict__ ids_prev,
    int N, int M)
{
    __shared__ int   s_bx1[MAXM], s_by1[MAXM], s_bx2[MAXM], s_by2[MAXM];
    __shared__ float s_areap[MAXM], s_sp[MAXM], s_fp[MAXM];
    __shared__ int   s_idp[MAXM];
    __shared__ int   s_matched[MAXM];

    int t = threadIdx.x;

    // Load prev-det data into shared (subsampled, floored int boxes)
    for (int j = t; j < M; j += blockDim.x) {
        int x1 = (int)floorf(boxes_prev[4*j+0] * 0.5f);
        int y1 = (int)floorf(boxes_prev[4*j+1] * 0.5f);
        int x2 = (int)floorf(boxes_prev[4*j+2] * 0.5f);
        int y2 = (int)floorf(boxes_prev[4*j+3] * 0.5f);
        s_bx1[j] = x1; s_by1[j] = y1; s_bx2[j] = x2; s_by2[j] = y2;
        s_areap[j] = (float)(x2 - x1) * (float)(y2 - y1);
        s_sp[j] = scores_prev[j];
        s_fp[j] = flags_prev[j];
        s_idp[j] = ids_prev[j];
        s_matched[j] = 0;
    }
    __syncthreads();

    if (t < N) {
        int bx1 = (int)floorf(boxes[4*t+0] * 0.5f);
        int by1 = (int)floorf(boxes[4*t+1] * 0.5f);
        int bx2 = (int)floorf(boxes[4*t+2] * 0.5f);
        int by2 = (int)floorf(boxes[4*t+3] * 0.5f);
        float area = (float)(bx2 - bx1) * (float)(by2 - by1);
        int myid = ids[t];

        // first id match (jnp.argmax over bool eq -> first True, default 0)
        int midx = 0; bool hasm = false;
        for (int j = 0; j < M; j++) {
            if (s_idp[j] == myid) { midx = j; hasm = true; break; }
        }

        // scan all prev dets: IoU, best-excl-id (first-argmax), IoU at midx
        float best = -3.0f; int bidx = 0; float ioum = 0.0f;
        for (int j = 0; j < M; j++) {
            int ix1 = max(bx1, s_bx1[j]);
            int iy1 = max(by1, s_by1[j]);
            int ix2 = min(bx2, s_bx2[j]);
            int iy2 = min(by2, s_by2[j]);
            float iw = (float)max(ix2 - ix1, 0);
            float ih = (float)max(iy2 - iy1, 0);
            float inter = iw * ih;
            float iou = inter / (area + s_areap[j] - inter);
            float v = (s_idp[j] == myid) ? -1.0f : iou;
            if (v > best) { best = v; bidx = j; }   // strict > keeps first max
            if (j == midx) ioum = iou;
        }

        float fl = flags[t];
        float sc = scores[t];
        bool  flag1    = (fl == 1.0f);
        bool  has_best = (best > 0.0f);
        float best_iou = fmaxf(best, 0.0f);
        float ig1 = 1.0f - best_iou;
        float ig0 = 1.0f - ioum;

        // rect[t]: current box
        float val_cur = flag1 ? (ig1 * sc) : (ig0 * sc * (1.0f - fl));
        g_rx1[t] = bx1; g_ry1[t] = by1; g_rx2[t] = bx2; g_ry2[t] = by2;
        g_rval[t] = val_cur;

        // rect[N+t]: associated prev box
        float sp1 = s_sp[bidx], fp1 = s_fp[bidx];
        float v1 = ig1 * ((fp1 == 1.0f) ? sp1 : sp1 * (1.0f - fp1));
        float sp0 = s_sp[midx], fp0 = s_fp[midx];
        float v0 = ig0 * ((fp0 == 1.0f) ? sp0 : sp0 * (1.0f - fl)); // (1 - current flag), per source
        int   pj   = flag1 ? bidx : midx;
        float pv   = flag1 ? v1 : v0;
        bool  pact = flag1 ? has_best : hasm;
        g_rx1[N+t] = s_bx1[pj]; g_ry1[N+t] = s_by1[pj];
        g_rx2[N+t] = s_bx2[pj]; g_ry2[N+t] = s_by2[pj];
        g_rval[N+t] = pact ? pv : 0.0f;
        if (pact) atomicExch(&s_matched[pj], 1);
    }
    __syncthreads();

    // rect[2N+j]: leftover (unmatched) prev dets
    for (int j = t; j < M; j += blockDim.x) {
        float spv = s_sp[j], fpv = s_fp[j];
        float vu = (fpv == 1.0f) ? spv : spv * (1.0f - fpv);
        g_rx1[2*N+j] = s_bx1[j]; g_ry1[2*N+j] = s_by1[j];
        g_rx2[2*N+j] = s_bx2[j]; g_ry2[2*N+j] = s_by2[j];
        g_rval[2*N+j] = s_matched[j] ? 0.0f : vu;
    }
}

// Tile: 64 (x) x 16 (y) sub-pixels per block, 256 threads, each owns a 2x2
// sub-pixel patch -> writes a 4x4 full-res patch via 4 float4 stores.
__global__ void __launch_bounds__(256) paint_kernel(float* __restrict__ out, int K)
{
    __shared__ int   cx1[MAXK], cy1[MAXK], cx2[MAXK], cy2[MAXK];
    __shared__ float cval[MAXK];
    __shared__ int scount;

    int t = threadIdx.x;
    if (t == 0) scount = 0;
    __syncthreads();

    int tx0 = blockIdx.x * 64;
    int ty0 = blockIdx.y * 16;

    // Cull rects into shared compact list
    for (int r = t; r < K; r += blockDim.x) {
        int x1 = g_rx1[r], y1 = g_ry1[r], x2 = g_rx2[r], y2 = g_ry2[r];
        float v = g_rval[r];
        if (v > 0.0f && x1 < tx0 + 64 && x2 > tx0 && y1 < ty0 + 16 && y2 > ty0) {
            int idx = atomicAdd(&scount, 1);
            cx1[idx] = x1; cy1[idx] = y1; cx2[idx] = x2; cy2[idx] = y2;
            cval[idx] = v;
        }
    }
    __syncthreads();

    int sx = tx0 + ((t & 31) << 1);
    int sy = ty0 + ((t >> 5) << 1);

    float v00 = 0.0f, v01 = 0.0f, v10 = 0.0f, v11 = 0.0f;
    int n = scount;
    for (int r = 0; r < n; r++) {
        int x1 = cx1[r], y1 = cy1[r], x2 = cx2[r], y2 = cy2[r];
        float v = cval[r];
        bool inx0 = (sx     >= x1) & (sx     < x2);
        bool inx1 = (sx + 1 >= x1) & (sx + 1 < x2);
        bool iny0 = (sy     >= y1) & (sy     < y2);
        bool iny1 = (sy + 1 >= y1) & (sy + 1 < y2);
        if (inx0 & iny0) v00 = fmaxf(v00, v);
        if (inx1 & iny0) v01 = fmaxf(v01, v);
        if (inx0 & iny1) v10 = fmaxf(v10, v);
        if (inx1 & iny1) v11 = fmaxf(v11, v);
    }

    if (sy < HS) {  // last block row is partial in y (1080 = 67*16 + 8)
        int gx = sx << 1;
        int gy = sy << 1;
        float4 a = make_float4(v00, v00, v01, v01);
        float4 b = make_float4(v10, v10, v11, v11);
        float4* p0 = (float4*)(out + (size_t)(gy    ) * OUTW + gx);
        float4* p1 = (float4*)(out + (size_t)(gy + 1) * OUTW + gx);
        float4* p2 = (float4*)(out + (size_t)(gy + 2) * OUTW + gx);
        float4* p3 = (float4*)(out + (size_t)(gy + 3) * OUTW + gx);
        *p0 = a; *p1 = a;
        *p2 = b; *p3 = b;
    }
}

extern "C" void kernel_launch(void* const* d_in, const int* in_sizes, int n_in,
                              void* d_out, int out_size)
{
    // metadata order: inputs, boxes, scores, flags, boxes_prev, scores_prev,
    //                 flags_prev, ids, ids_prev
    const float* boxes       = (const float*)d_in[1];
    const float* scores      = (const float*)d_in[2];
    const float* flags       = (const float*)d_in[3];
    const float* boxes_prev  = (const float*)d_in[4];
    const float* scores_prev = (const float*)d_in[5];
    const float* flags_prev  = (const float*)d_in[6];
    const int*   ids         = (const int*)d_in[7];
    const int*   ids_prev    = (const int*)d_in[8];

    int N = in_sizes[2];   // scores element count
    int M = in_sizes[5];   // scores_prev element count

    setup_kernel<<<1, 256>>>(boxes, scores, flags, boxes_prev, scores_prev,
                             flags_prev, ids, ids_prev, N, M);

    dim3 grid(WS / 64, (HS + 15) / 16);   // 30 x 68
    paint_kernel<<<grid, 256>>>((float*)d_out, 2 * N + M);
}

// round 3
// speedup vs baseline: 2.0454x; 2.0454x over previous
#include <cuda_runtime.h>
#include <math.h>

#define HS 1080
#define WS 1920
#define OUTW 3840
#define MAXN 256
#define MAXM 256
#define MAXK (2*MAXN + MAXM)
#define SUBS 8
#define DETS_PER_BLK 32

// Rect table scratch (allocation-free: __device__ globals)
__device__ int4  g_rbox[MAXK];   // subsampled int boxes (x1,y1,x2,y2)
__device__ float g_rval[MAXK];   // paint value (<=0 -> culled)
__device__ int   g_pj[MAXN];     // matched prev index per current det, -1 if inactive

__global__ void __launch_bounds__(256) setup_kernel(
    const float4* __restrict__ boxes, const float* __restrict__ scores,
    const float* __restrict__ flags,
    const float4* __restrict__ boxes_prev, const float* __restrict__ scores_prev,
    const float* __restrict__ flags_prev,
    const int* __restrict__ ids, const int* __restrict__ ids_prev,
    int N, int M)
{
    __shared__ float4 s_pb[MAXM];                 // floored prev boxes
    __shared__ float  s_parea[MAXM], s_ps[MAXM], s_pf[MAXM];
    __shared__ int    s_pid[MAXM];
    __shared__ float  p_best[256], p_ioum[256];
    __shared__ int    p_bidx[256], p_midx[256];

    int t = threadIdx.x;

    // Load prev-det data into shared (subsampled, floored boxes kept as floats)
    for (int j = t; j < M; j += blockDim.x) {
        float4 b = boxes_prev[j];
        float x1 = floorf(b.x * 0.5f), y1 = floorf(b.y * 0.5f);
        float x2 = floorf(b.z * 0.5f), y2 = floorf(b.w * 0.5f);
        s_pb[j] = make_float4(x1, y1, x2, y2);
        s_parea[j] = (x2 - x1) * (y2 - y1);
        s_ps[j] = scores_prev[j];
        s_pf[j] = flags_prev[j];
        s_pid[j] = ids_prev[j];
    }
    __syncthreads();

    int det = blockIdx.x * DETS_PER_BLK + (t >> 3);  // 8 threads per det
    int sub = t & 7;

    float bx1 = 0.f, by1 = 0.f, bx2 = 0.f, by2 = 0.f;

    if (det < N) {
        float4 b = boxes[det];
        bx1 = floorf(b.x * 0.5f); by1 = floorf(b.y * 0.5f);
        bx2 = floorf(b.z * 0.5f); by2 = floorf(b.w * 0.5f);
        float area = (bx2 - bx1) * (by2 - by1);
        int myid = ids[det];

        int chunk = (M + SUBS - 1) / SUBS;
        int j0 = sub * chunk;
        int j1 = min(M, j0 + chunk);

        float best = -3.0f, ioum = 0.0f, iou0 = 0.0f;
        int bidx = 0, midx = -1;
        for (int j = j0; j < j1; j++) {
            float4 p = s_pb[j];
            float ix1 = fmaxf(bx1, p.x), iy1 = fmaxf(by1, p.y);
            float ix2 = fminf(bx2, p.z), iy2 = fminf(by2, p.w);
            float inter = fmaxf(ix2 - ix1, 0.0f) * fmaxf(iy2 - iy1, 0.0f);
            float iou = inter / (area + s_parea[j] - inter);  // exact IEEE div, matches jnp
            bool ism = (s_pid[j] == myid);
            if (ism) { midx = j; ioum = iou; }
            float v = ism ? -1.0f : iou;
            if (v > best) { best = v; bidx = j; }  // strict > keeps first argmax
            if (j == 0) iou0 = iou;                // only sub 0 ever hits j==0
        }
        // reference: no id match -> midx=0, iou_m = iou[i][0] (sub 0's iou0)
        if (midx < 0) ioum = iou0;

        p_best[t] = best; p_bidx[t] = bidx;
        p_ioum[t] = ioum; p_midx[t] = midx;
    }
    __syncthreads();

    if (det < N && sub == 0) {
        float best = -3.0f, ioum = p_ioum[t];
        int bidx = 0, midx = 0;
        bool hasm = false;
        #pragma unroll
        for (int s = 0; s < SUBS; s++) {
            float b = p_best[t + s];
            if (b > best) { best = b; bidx = p_bidx[t + s]; }  // chunks ascend: first-argmax
            if (!hasm && p_midx[t + s] >= 0) {
                hasm = true; midx = p_midx[t + s]; ioum = p_ioum[t + s];
            }
        }

        float fl = flags[det];
        float sc = scores[det];
        bool  flag1    = (fl == 1.0f);
        bool  has_best = (best > 0.0f);
        float best_iou = fmaxf(best, 0.0f);
        float ig1 = 1.0f - best_iou;
        float ig0 = 1.0f - ioum;

        // rect[det]: current box
        float val_cur = flag1 ? (ig1 * sc) : (ig0 * sc * (1.0f - fl));
        g_rbox[det] = make_int4((int)bx1, (int)by1, (int)bx2, (int)by2);
        g_rval[det] = val_cur;

        // rect[N+det]: associated prev box
        float sp1 = s_ps[bidx], fp1 = s_pf[bidx];
        float v1 = ig1 * ((fp1 == 1.0f) ? sp1 : sp1 * (1.0f - fp1));
        float sp0 = s_ps[midx], fp0 = s_pf[midx];
        float v0 = ig0 * ((fp0 == 1.0f) ? sp0 : sp0 * (1.0f - fl)); // (1 - current flag), per source
        int   pj   = flag1 ? bidx : midx;
        float pv   = flag1 ? v1 : v0;
        bool  pact = flag1 ? has_best : hasm;
        float4 pb = s_pb[pj];
        g_rbox[N + det] = make_int4((int)pb.x, (int)pb.y, (int)pb.z, (int)pb.w);
        g_rval[N + det] = pact ? pv : 0.0f;
        g_pj[det] = pact ? pj : -1;
    }

    // rect[2N+j]: prev boxes with leftover value; paint masks by matched flag
    if (blockIdx.x == 0) {
        for (int j = t; j < M; j += blockDim.x) {
            float spv = s_ps[j], fpv = s_pf[j];
            float vu = (fpv == 1.0f) ? spv : spv * (1.0f - fpv);
            float4 pb = s_pb[j];
            g_rbox[2 * N + j] = make_int4((int)pb.x, (int)pb.y, (int)pb.z, (int)pb.w);
            g_rval[2 * N + j] = vu;
        }
    }
}

// Tile: 128 (x) x 32 (y) sub-pixels per block, 256 threads, each owns a 4x4
// sub-pixel patch -> writes an 8x8 full-res patch via 16 float4 stores.
__global__ void __launch_bounds__(256) paint_kernel(float* __restrict__ out, int N, int M)
{
    __shared__ int4  c_box[MAXK];
    __shared__ float c_val[MAXK];
    __shared__ int   s_matched[MAXM];
    __shared__ int   scount;

    int t = threadIdx.x;
    if (t == 0) scount = 0;
    for (int j = t; j < M; j += blockDim.x) s_matched[j] = 0;
    __syncthreads();

    // reconstruct matched[] from per-det matched prev index
    for (int i = t; i < N; i += blockDim.x) {
        int pj = g_pj[i];
        if (pj >= 0) s_matched[pj] = 1;   // benign races: same value
    }
    __syncthreads();

    int tx0 = blockIdx.x * 128;
    int ty0 = blockIdx.y * 32;
    int K = 2 * N + M;

    // Cull rects into shared compact list
    for (int r = t; r < K; r += blockDim.x) {
        int4 b = g_rbox[r];
        float v = g_rval[r];
        if (r >= 2 * N && s_matched[r - 2 * N]) v = 0.0f;
        if (v > 0.0f && b.x < tx0 + 128 && b.z > tx0 && b.y < ty0 + 32 && b.w > ty0) {
            int idx = atomicAdd(&scount, 1);
            c_box[idx] = b;
            c_val[idx] = v;
        }
    }
    __syncthreads();

    int sx = tx0 + ((t & 31) << 2);
    int sy = ty0 + ((t >> 5) << 2);

    float v[4][4];
    #pragma unroll
    for (int r = 0; r < 4; r++)
        #pragma unroll
        for (int c = 0; c < 4; c++) v[r][c] = 0.0f;

    int n = scount;
    for (int r = 0; r < n; r++) {
        int4 b = c_box[r];
        float val = c_val[r];
        bool cx[4], cy[4];
        #pragma unroll
        for (int c = 0; c < 4; c++) cx[c] = (sx + c >= b.x) & (sx + c < b.z);
        #pragma unroll
        for (int rr = 0; rr < 4; rr++) cy[rr] = (sy + rr >= b.y) & (sy + rr < b.w);
        #pragma unroll
        for (int rr = 0; rr < 4; rr++)
            #pragma unroll
            for (int c = 0; c < 4; c++)
                if (cy[rr] & cx[c]) v[rr][c] = fmaxf(v[rr][c], val);
    }

    int gx = sx << 1;
    #pragma unroll
    for (int rr = 0; rr < 4; rr++) {
        int syr = sy + rr;
        if (syr < HS) {
            int gy = syr << 1;
            float4 lo = make_float4(v[rr][0], v[rr][0], v[rr][1], v[rr][1]);
            float4 hi = make_float4(v[rr][2], v[rr][2], v[rr][3], v[rr][3]);
            float4* p0 = (float4*)(out + (size_t)gy * OUTW + gx);
            float4* p1 = (float4*)(out + (size_t)(gy + 1) * OUTW + gx);
            p0[0] = lo; p0[1] = hi;
            p1[0] = lo; p1[1] = hi;
        }
    }
}

extern "C" void kernel_launch(void* const* d_in, const int* in_sizes, int n_in,
                              void* d_out, int out_size)
{
    // metadata order: inputs, boxes, scores, flags, boxes_prev, scores_prev,
    //                 flags_prev, ids, ids_prev
    const float4* boxes      = (const float4*)d_in[1];
    const float*  scores     = (const float*)d_in[2];
    const float*  flags      = (const float*)d_in[3];
    const float4* boxes_prev = (const float4*)d_in[4];
    const float*  scores_prev= (const float*)d_in[5];
    const float*  flags_prev = (const float*)d_in[6];
    const int*    ids        = (const int*)d_in[7];
    const int*    ids_prev   = (const int*)d_in[8];

    int N = in_sizes[2];   // scores element count
    int M = in_sizes[5];   // scores_prev element count

    int setup_blocks = (N + DETS_PER_BLK - 1) / DETS_PER_BLK;
    setup_kernel<<<setup_blocks, 256>>>(boxes, scores, flags, boxes_prev, scores_prev,
                                        flags_prev, ids, ids_prev, N, M);

    dim3 grid(WS / 128, (HS + 31) / 32);   // 15 x 34
    paint_kernel<<<grid, 256>>>((float*)d_out, N, M);
}

// round 7
// speedup vs baseline: 2.5203x; 1.2322x over previous
#include <cuda_runtime.h>
#include <math.h>

#define HS 1080
#define WS 1920
#define OUTW 3840
#define MAXN 256
#define MAXM 256
#define MAXK (2*MAXN + MAXM)
#define SUBS 8
#define DETS_PER_BLK 32

// Rect table scratch (allocation-free: __device__ globals)
__device__ int4  g_rbox[MAXK];   // subsampled int boxes (x1,y1,x2,y2)
__device__ float g_rval[MAXK];   // paint value (<=0 -> culled)
__device__ int   g_pj[MAXN];     // matched prev index per current det, -1 if inactive

__global__ void __launch_bounds__(256) setup_kernel(
    const float4* __restrict__ boxes, const float* __restrict__ scores,
    const float* __restrict__ flags,
    const float4* __restrict__ boxes_prev, const float* __restrict__ scores_prev,
    const float* __restrict__ flags_prev,
    const int* __restrict__ ids, const int* __restrict__ ids_prev,
    int N, int M)
{
    __shared__ float4 s_pb[MAXM];                 // floored prev boxes
    __shared__ float  s_parea[MAXM], s_ps[MAXM], s_pf[MAXM];
    __shared__ int    s_pid[MAXM];
    __shared__ float  p_best[256], p_ioum[256];
    __shared__ int    p_bidx[256], p_midx[256];

    int t = threadIdx.x;

    // Load prev-det data into shared (subsampled, floored boxes kept as floats)
    for (int j = t; j < M; j += blockDim.x) {
        float4 b = boxes_prev[j];
        float x1 = floorf(b.x * 0.5f), y1 = floorf(b.y * 0.5f);
        float x2 = floorf(b.z * 0.5f), y2 = floorf(b.w * 0.5f);
        s_pb[j] = make_float4(x1, y1, x2, y2);
        s_parea[j] = (x2 - x1) * (y2 - y1);
        s_ps[j] = scores_prev[j];
        s_pf[j] = flags_prev[j];
        s_pid[j] = ids_prev[j];
    }
    __syncthreads();

    int det = blockIdx.x * DETS_PER_BLK + (t >> 3);  // 8 threads per det
    int sub = t & 7;

    float bx1 = 0.f, by1 = 0.f, bx2 = 0.f, by2 = 0.f;

    if (det < N) {
        float4 b = boxes[det];
        bx1 = floorf(b.x * 0.5f); by1 = floorf(b.y * 0.5f);
        bx2 = floorf(b.z * 0.5f); by2 = floorf(b.w * 0.5f);
        float area = (bx2 - bx1) * (by2 - by1);
        int myid = ids[det];

        int chunk = (M + SUBS - 1) / SUBS;
        int j0 = sub * chunk;
        int j1 = min(M, j0 + chunk);

        float best = -3.0f, ioum = 0.0f, iou0 = 0.0f;
        int bidx = 0, midx = -1;
        for (int j = j0; j < j1; j++) {
            float4 p = s_pb[j];
            float ix1 = fmaxf(bx1, p.x), iy1 = fmaxf(by1, p.y);
            float ix2 = fminf(bx2, p.z), iy2 = fminf(by2, p.w);
            float inter = fmaxf(ix2 - ix1, 0.0f) * fmaxf(iy2 - iy1, 0.0f);
            float iou = inter / (area + s_parea[j] - inter);  // exact IEEE div, matches jnp
            bool ism = (s_pid[j] == myid);
            if (ism) { midx = j; ioum = iou; }
            float v = ism ? -1.0f : iou;
            if (v > best) { best = v; bidx = j; }  // strict > keeps first argmax
            if (j == 0) iou0 = iou;                // only sub 0 ever hits j==0
        }
        // reference: no id match -> midx=0, iou_m = iou[i][0] (sub 0's iou0)
        if (midx < 0) ioum = iou0;

        p_best[t] = best; p_bidx[t] = bidx;
        p_ioum[t] = ioum; p_midx[t] = midx;
    }
    __syncthreads();

    if (det < N && sub == 0) {
        float best = -3.0f, ioum = p_ioum[t];
        int bidx = 0, midx = 0;
        bool hasm = false;
        #pragma unroll
        for (int s = 0; s < SUBS; s++) {
            float b = p_best[t + s];
            if (b > best) { best = b; bidx = p_bidx[t + s]; }  // chunks ascend: first-argmax
            if (!hasm && p_midx[t + s] >= 0) {
                hasm = true; midx = p_midx[t + s]; ioum = p_ioum[t + s];
            }
        }

        float fl = flags[det];
        float sc = scores[det];
        bool  flag1    = (fl == 1.0f);
        bool  has_best = (best > 0.0f);
        float best_iou = fmaxf(best, 0.0f);
        float ig1 = 1.0f - best_iou;
        float ig0 = 1.0f - ioum;

        // rect[det]: current box
        float val_cur = flag1 ? (ig1 * sc) : (ig0 * sc * (1.0f - fl));
        g_rbox[det] = make_int4((int)bx1, (int)by1, (int)bx2, (int)by2);
        g_rval[det] = val_cur;

        // rect[N+det]: associated prev box
        float sp1 = s_ps[bidx], fp1 = s_pf[bidx];
        float v1 = ig1 * ((fp1 == 1.0f) ? sp1 : sp1 * (1.0f - fp1));
        float sp0 = s_ps[midx], fp0 = s_pf[midx];
        float v0 = ig0 * ((fp0 == 1.0f) ? sp0 : sp0 * (1.0f - fl)); // (1 - current flag), per source
        int   pj   = flag1 ? bidx : midx;
        float pv   = flag1 ? v1 : v0;
        bool  pact = flag1 ? has_best : hasm;
        float4 pb = s_pb[pj];
        g_rbox[N + det] = make_int4((int)pb.x, (int)pb.y, (int)pb.z, (int)pb.w);
        g_rval[N + det] = pact ? pv : 0.0f;
        g_pj[det] = pact ? pj : -1;
    }

    // rect[2N+j]: prev boxes with leftover value (unmasked; finalize masks)
    if (blockIdx.x == 0) {
        for (int j = t; j < M; j += blockDim.x) {
            float spv = s_ps[j], fpv = s_pf[j];
            float vu = (fpv == 1.0f) ? spv : spv * (1.0f - fpv);
            float4 pb = s_pb[j];
            g_rbox[2 * N + j] = make_int4((int)pb.x, (int)pb.y, (int)pb.z, (int)pb.w);
            g_rval[2 * N + j] = vu;
        }
    }
}

// Zero out leftover-prev rect values for matched prev dets (1 block, O(N)).
__global__ void __launch_bounds__(256) finalize_kernel(int N)
{
    int i = threadIdx.x;
    if (i < N) {
        int pj = g_pj[i];
        if (pj >= 0) g_rval[2 * N + pj] = 0.0f;   // races benign: same value
    }
}

// Tile: 64 (x) x 16 (y) sub-pixels per block, 256 threads, each owns a 2x2
// sub-pixel patch -> writes a 4x4 full-res patch via 4 float4 stores.
__global__ void __launch_bounds__(256) paint_kernel(float* __restrict__ out, int K)
{
    __shared__ int4  c_box[MAXK];
    __shared__ float c_val[MAXK];
    __shared__ int   scount;

    int t = threadIdx.x;
    if (t == 0) scount = 0;
    __syncthreads();

    int tx0 = blockIdx.x * 64;
    int ty0 = blockIdx.y * 16;

    // Cull rects into shared compact list
    for (int r = t; r < K; r += blockDim.x) {
        float v = g_rval[r];
        int4 b = g_rbox[r];
        if (v > 0.0f && b.x < tx0 + 64 && b.z > tx0 && b.y < ty0 + 16 && b.w > ty0) {
            int idx = atomicAdd(&scount, 1);
            c_box[idx] = b;
            c_val[idx] = v;
        }
    }
    __syncthreads();

    int sx = tx0 + ((t & 31) << 1);
    int sy = ty0 + ((t >> 5) << 1);

    float v00 = 0.0f, v01 = 0.0f, v10 = 0.0f, v11 = 0.0f;
    int n = scount;
    for (int r = 0; r < n; r++) {
        int4 b = c_box[r];
        float v = c_val[r];
        bool inx0 = (sx     >= b.x) & (sx     < b.z);
        bool inx1 = (sx + 1 >= b.x) & (sx + 1 < b.z);
        bool iny0 = (sy     >= b.y) & (sy     < b.w);
        bool iny1 = (sy + 1 >= b.y) & (sy + 1 < b.w);
        if (inx0 & iny0) v00 = fmaxf(v00, v);
        if (inx1 & iny0) v01 = fmaxf(v01, v);
        if (inx0 & iny1) v10 = fmaxf(v10, v);
        if (inx1 & iny1) v11 = fmaxf(v11, v);
    }

    if (sy < HS) {  // last block row is partial in y (1080 = 67*16 + 8)
        int gx = sx << 1;
        int gy = sy << 1;
        float4 a = make_float4(v00, v00, v01, v01);
        float4 b = make_float4(v10, v10, v11, v11);
        float4* p0 = (float4*)(out + (size_t)(gy    ) * OUTW + gx);
        float4* p1 = (float4*)(out + (size_t)(gy + 1) * OUTW + gx);
        float4* p2 = (float4*)(out + (size_t)(gy + 2) * OUTW + gx);
        float4* p3 = (float4*)(out + (size_t)(gy + 3) * OUTW + gx);
        *p0 = a; *p1 = a;
        *p2 = b; *p3 = b;
    }
}

extern "C" void kernel_launch(void* const* d_in, const int* in_sizes, int n_in,
                              void* d_out, int out_size)
{
    // metadata order: inputs, boxes, scores, flags, boxes_prev, scores_prev,
    //                 flags_prev, ids, ids_prev
    const float4* boxes      = (const float4*)d_in[1];
    const float*  scores     = (const float*)d_in[2];
    const float*  flags      = (const float*)d_in[3];
    const float4* boxes_prev = (const float4*)d_in[4];
    const float*  scores_prev= (const float*)d_in[5];
    const float*  flags_prev = (const float*)d_in[6];
    const int*    ids        = (const int*)d_in[7];
    const int*    ids_prev   = (const int*)d_in[8];

    int N = in_sizes[2];   // scores element count
    int M = in_sizes[5];   // scores_prev element count

    int setup_blocks = (N + DETS_PER_BLK - 1) / DETS_PER_BLK;
    setup_kernel<<<setup_blocks, 256>>>(boxes, scores, flags, boxes_prev, scores_prev,
                                        flags_prev, ids, ids_prev, N, M);

    finalize_kernel<<<1, 256>>>(N);

    dim3 grid(WS / 64, (HS + 15) / 16);   // 30 x 68
    paint_kernel<<<grid, 256>>>((float*)d_out, 2 * N + M);
}